// round 1
// baseline (speedup 1.0000x reference)
#include <cuda_runtime.h>

#define BB 4
#define NN 2048
#define DD 512
#define HH 8
#define HD 64
#define TEMP 8.0f

#define BQ 64
#define BK 64
#define LD 68   // padded smem leading dim (floats)

// scratch for attention output (pre-projection), layout (B, N, D) with D = h*64+hd
__device__ float g_att[(size_t)BB * NN * DD];

// ---------------------------------------------------------------------------
// Fused attention: one block = one (b, h, 64-query tile).
// S = Q K^T / T, P = exp(S) (no max shift: logits ~ N(0,1), safe in fp32),
// O = (P V) / rowsum(P). rowsum accumulated in registers across all K tiles.
// ---------------------------------------------------------------------------
__global__ __launch_bounds__(256) void attn_kernel(const float* __restrict__ Kg,
                                                   const float* __restrict__ Qg,
                                                   const float* __restrict__ Vg) {
    extern __shared__ float sm[];
    float (*Qt)[LD] = (float(*)[LD])sm;                    // Qt[k][r]
    float (*Kt)[LD] = (float(*)[LD])(sm + 1 * HD * LD);    // Kt[k][c]
    float (*Vs)[LD] = (float(*)[LD])(sm + 2 * HD * LD);    // Vs[c][d]
    float (*Ss)[LD] = (float(*)[LD])(sm + 3 * HD * LD);    // P[r][c]
    float* Ls = sm + 4 * HD * LD;                          // rowsum [64]

    const int qt = blockIdx.x;          // 0..31
    const int h  = blockIdx.y;
    const int b  = blockIdx.z;
    const int t  = threadIdx.x;
    const int tx = t & 15, ty = t >> 4;
    const int r0 = ty * 4, c0 = tx * 4;
    const int q0 = qt * BQ;

    const float* Qbase = Qg + ((size_t)b * NN) * DD + h * HD;
    const float* Kbase = Kg + ((size_t)b * NN) * DD + h * HD;
    const float* Vbase = Vg + ((size_t)b * NN) * DD + h * HD;

    // Load Q tile transposed: Qt[k][r] = Q[q0+r][k]
    for (int i = t; i < BQ * (HD / 4); i += 256) {
        int r  = i >> 4;
        int k4 = (i & 15) << 2;
        float4 v = *(const float4*)(Qbase + (size_t)(q0 + r) * DD + k4);
        Qt[k4 + 0][r] = v.x; Qt[k4 + 1][r] = v.y;
        Qt[k4 + 2][r] = v.z; Qt[k4 + 3][r] = v.w;
    }

    float o[4][4] = {};
    float lsum[4] = {0.f, 0.f, 0.f, 0.f};
    const float inv_temp = 1.0f / TEMP;

    for (int kt = 0; kt < NN; kt += BK) {
        __syncthreads();  // protect Kt/Vs/Ss before overwrite (also covers Q load)

        // Load K tile transposed + V tile natural
        for (int i = t; i < BK * (HD / 4); i += 256) {
            int c  = i >> 4;
            int k4 = (i & 15) << 2;
            float4 v = *(const float4*)(Kbase + (size_t)(kt + c) * DD + k4);
            Kt[k4 + 0][c] = v.x; Kt[k4 + 1][c] = v.y;
            Kt[k4 + 2][c] = v.z; Kt[k4 + 3][c] = v.w;
            float4 w = *(const float4*)(Vbase + (size_t)(kt + c) * DD + k4);
            *(float4*)&Vs[c][k4] = w;
        }
        __syncthreads();

        // S = Q K^T (4x4 micro-tile per thread)
        float s[4][4] = {};
        #pragma unroll 8
        for (int k = 0; k < HD; ++k) {
            float4 qv = *(const float4*)&Qt[k][r0];
            float4 kv = *(const float4*)&Kt[k][c0];
            s[0][0] += qv.x * kv.x; s[0][1] += qv.x * kv.y; s[0][2] += qv.x * kv.z; s[0][3] += qv.x * kv.w;
            s[1][0] += qv.y * kv.x; s[1][1] += qv.y * kv.y; s[1][2] += qv.y * kv.z; s[1][3] += qv.y * kv.w;
            s[2][0] += qv.z * kv.x; s[2][1] += qv.z * kv.y; s[2][2] += qv.z * kv.z; s[2][3] += qv.z * kv.w;
            s[3][0] += qv.w * kv.x; s[3][1] += qv.w * kv.y; s[3][2] += qv.w * kv.z; s[3][3] += qv.w * kv.w;
        }

        // P = exp(S / T), accumulate per-thread partial rowsums, store P to smem
        #pragma unroll
        for (int i = 0; i < 4; ++i) {
            float4 p;
            p.x = __expf(s[i][0] * inv_temp);
            p.y = __expf(s[i][1] * inv_temp);
            p.z = __expf(s[i][2] * inv_temp);
            p.w = __expf(s[i][3] * inv_temp);
            lsum[i] += (p.x + p.y) + (p.z + p.w);
            *(float4*)&Ss[r0 + i][c0] = p;
        }
        __syncthreads();

        // O += P V
        #pragma unroll 8
        for (int c = 0; c < BK; ++c) {
            float4 vv = *(const float4*)&Vs[c][c0];
            float p0 = Ss[r0 + 0][c];
            float p1 = Ss[r0 + 1][c];
            float p2 = Ss[r0 + 2][c];
            float p3 = Ss[r0 + 3][c];
            o[0][0] += p0 * vv.x; o[0][1] += p0 * vv.y; o[0][2] += p0 * vv.z; o[0][3] += p0 * vv.w;
            o[1][0] += p1 * vv.x; o[1][1] += p1 * vv.y; o[1][2] += p1 * vv.z; o[1][3] += p1 * vv.w;
            o[2][0] += p2 * vv.x; o[2][1] += p2 * vv.y; o[2][2] += p2 * vv.z; o[2][3] += p2 * vv.w;
            o[3][0] += p3 * vv.x; o[3][1] += p3 * vv.y; o[3][2] += p3 * vv.z; o[3][3] += p3 * vv.w;
        }
    }

    // Reduce rowsums across the 16 tx lanes (each row owned by exactly one warp)
    #pragma unroll
    for (int i = 0; i < 4; ++i) {
        float v = lsum[i];
        v += __shfl_xor_sync(0xffffffffu, v, 1);
        v += __shfl_xor_sync(0xffffffffu, v, 2);
        v += __shfl_xor_sync(0xffffffffu, v, 4);
        v += __shfl_xor_sync(0xffffffffu, v, 8);
        if (tx == 0) Ls[r0 + i] = v;
    }
    __syncthreads();

    // Normalize and write to scratch
    float* Obase = g_att + ((size_t)b * NN + q0) * DD + h * HD;
    #pragma unroll
    for (int i = 0; i < 4; ++i) {
        float inv_l = 1.0f / Ls[r0 + i];
        float4 w;
        w.x = o[i][0] * inv_l;
        w.y = o[i][1] * inv_l;
        w.z = o[i][2] * inv_l;
        w.w = o[i][3] * inv_l;
        *(float4*)(Obase + (size_t)(r0 + i) * DD + c0) = w;
    }
}

// ---------------------------------------------------------------------------
// Projection: out[m][n] = bias[n] + sum_k X[m][k] * W[n][k]
// X = g_att (8192 x 512), W row-major (512 x 512).
// ---------------------------------------------------------------------------
__global__ __launch_bounds__(256) void proj_kernel(const float* __restrict__ Wc,
                                                   const float* __restrict__ bias,
                                                   float* __restrict__ out) {
    __shared__ float Xt[64][LD];   // Xt[k][r]
    __shared__ float Wt[64][LD];   // Wt[k][c]

    const int n0 = blockIdx.x * 64;
    const int m0 = blockIdx.y * 64;
    const int t  = threadIdx.x;
    const int tx = t & 15, ty = t >> 4;
    const int r0 = ty * 4, c0 = tx * 4;

    float acc[4][4] = {};

    for (int k0 = 0; k0 < DD; k0 += 64) {
        __syncthreads();
        for (int i = t; i < 64 * 16; i += 256) {
            int r  = i >> 4;
            int k4 = (i & 15) << 2;
            float4 xv = *(const float4*)(g_att + (size_t)(m0 + r) * DD + k0 + k4);
            Xt[k4 + 0][r] = xv.x; Xt[k4 + 1][r] = xv.y;
            Xt[k4 + 2][r] = xv.z; Xt[k4 + 3][r] = xv.w;
            float4 wv = *(const float4*)(Wc + (size_t)(n0 + r) * DD + k0 + k4);
            Wt[k4 + 0][r] = wv.x; Wt[k4 + 1][r] = wv.y;
            Wt[k4 + 2][r] = wv.z; Wt[k4 + 3][r] = wv.w;
        }
        __syncthreads();

        #pragma unroll 8
        for (int k = 0; k < 64; ++k) {
            float4 xv = *(const float4*)&Xt[k][r0];
            float4 wv = *(const float4*)&Wt[k][c0];
            acc[0][0] += xv.x * wv.x; acc[0][1] += xv.x * wv.y; acc[0][2] += xv.x * wv.z; acc[0][3] += xv.x * wv.w;
            acc[1][0] += xv.y * wv.x; acc[1][1] += xv.y * wv.y; acc[1][2] += xv.y * wv.z; acc[1][3] += xv.y * wv.w;
            acc[2][0] += xv.z * wv.x; acc[2][1] += xv.z * wv.y; acc[2][2] += xv.z * wv.z; acc[2][3] += xv.z * wv.w;
            acc[3][0] += xv.w * wv.x; acc[3][1] += xv.w * wv.y; acc[3][2] += xv.w * wv.z; acc[3][3] += xv.w * wv.w;
        }
    }

    float4 bv = *(const float4*)(bias + n0 + c0);
    #pragma unroll
    for (int i = 0; i < 4; ++i) {
        float4 ov;
        ov.x = acc[i][0] + bv.x;
        ov.y = acc[i][1] + bv.y;
        ov.z = acc[i][2] + bv.z;
        ov.w = acc[i][3] + bv.w;
        *(float4*)(out + (size_t)(m0 + r0 + i) * DD + n0 + c0) = ov;
    }
}

extern "C" void kernel_launch(void* const* d_in, const int* in_sizes, int n_in,
                              void* d_out, int out_size) {
    const float* Kg   = (const float*)d_in[0];  // keys    (B, N, D)
    const float* Qg   = (const float*)d_in[1];  // queries (B, N, D)
    const float* Vg   = (const float*)d_in[2];  // values  (B, N, D)
    const float* Wc   = (const float*)d_in[3];  // W_comb  (D, D)
    const float* bias = (const float*)d_in[4];  // b_comb  (D,)
    float* out = (float*)d_out;                 // (B, N, D)

    const int smem_attn = (4 * HD * LD + 64) * (int)sizeof(float);  // ~70 KB
    cudaFuncSetAttribute(attn_kernel, cudaFuncAttributeMaxDynamicSharedMemorySize, smem_attn);

    dim3 agrid(NN / BQ, HH, BB);
    attn_kernel<<<agrid, 256, smem_attn>>>(Kg, Qg, Vg);

    dim3 pgrid(DD / 64, (BB * NN) / 64);
    proj_kernel<<<pgrid, 256>>>(Wc, bias, out);
}

// round 15
// speedup vs baseline: 2.0728x; 2.0728x over previous
#include <cuda_runtime.h>
#include <cuda_bf16.h>
#include <cstdint>

#define BB 4
#define NN 2048
#define DD 512
#define HH 8
#define HD 64

#define BM 128
#define BKV 128
#define NITER (NN / BKV)

#define STR 72  // smem row stride in bf16 (144 B, 16B-aligned rows)

// scratch for attention output (pre-projection), layout (B, N, D)
__device__ float g_att[(size_t)BB * NN * DD];

// smem byte offsets (all tiles 128 x STR bf16 = 18432 B)
#define OF_QH 0
#define OF_QL 18432
#define OF_KH 36864
#define OF_KL 55296
#define OF_VH 73728
#define OF_VL 92160
#define SMEM_SZ 110592

__device__ __forceinline__ uint32_t smem_u32(const void* p) {
    uint32_t a;
    asm("{ .reg .u64 t; cvta.to.shared.u64 t, %1; cvt.u32.u64 %0, t; }" : "=r"(a) : "l"(p));
    return a;
}

__device__ __forceinline__ void ldsm_x4(uint32_t* r, uint32_t addr) {
    asm volatile("ldmatrix.sync.aligned.m8n8.x4.shared.b16 {%0,%1,%2,%3}, [%4];"
                 : "=r"(r[0]), "=r"(r[1]), "=r"(r[2]), "=r"(r[3]) : "r"(addr));
}
__device__ __forceinline__ void ldsm_x2(uint32_t& r0, uint32_t& r1, uint32_t addr) {
    asm volatile("ldmatrix.sync.aligned.m8n8.x2.shared.b16 {%0,%1}, [%2];"
                 : "=r"(r0), "=r"(r1) : "r"(addr));
}
__device__ __forceinline__ void ldsm_x2t(uint32_t& r0, uint32_t& r1, uint32_t addr) {
    asm volatile("ldmatrix.sync.aligned.m8n8.x2.trans.shared.b16 {%0,%1}, [%2];"
                 : "=r"(r0), "=r"(r1) : "r"(addr));
}
__device__ __forceinline__ void mma16816(float* d, const uint32_t* a, uint32_t b0, uint32_t b1) {
    asm volatile(
        "mma.sync.aligned.m16n8k16.row.col.f32.bf16.bf16.f32 "
        "{%0,%1,%2,%3}, {%4,%5,%6,%7}, {%8,%9}, {%0,%1,%2,%3};"
        : "+f"(d[0]), "+f"(d[1]), "+f"(d[2]), "+f"(d[3])
        : "r"(a[0]), "r"(a[1]), "r"(a[2]), "r"(a[3]), "r"(b0), "r"(b1));
}

// split fp32x4 into hi/lo bf16x4 packed words
__device__ __forceinline__ void split4(const float* v, uint2& hi, uint2& lo) {
    __nv_bfloat16 h0 = __float2bfloat16(v[0]), h1 = __float2bfloat16(v[1]);
    __nv_bfloat16 h2 = __float2bfloat16(v[2]), h3 = __float2bfloat16(v[3]);
    float l0 = v[0] - __bfloat162float(h0), l1 = v[1] - __bfloat162float(h1);
    float l2 = v[2] - __bfloat162float(h2), l3 = v[3] - __bfloat162float(h3);
    hi.x = ((uint32_t)__bfloat16_as_ushort(h1) << 16) | __bfloat16_as_ushort(h0);
    hi.y = ((uint32_t)__bfloat16_as_ushort(h3) << 16) | __bfloat16_as_ushort(h2);
    __nv_bfloat16 g0 = __float2bfloat16(l0), g1 = __float2bfloat16(l1);
    __nv_bfloat16 g2 = __float2bfloat16(l2), g3 = __float2bfloat16(l3);
    lo.x = ((uint32_t)__bfloat16_as_ushort(g1) << 16) | __bfloat16_as_ushort(g0);
    lo.y = ((uint32_t)__bfloat16_as_ushort(g3) << 16) | __bfloat16_as_ushort(g2);
}
// split a pair of floats: hi word (lo16=a, hi16=b) + residual word
__device__ __forceinline__ void split2(float a, float b, uint32_t& hi, uint32_t& lo) {
    __nv_bfloat16 ha = __float2bfloat16(a), hb = __float2bfloat16(b);
    hi = ((uint32_t)__bfloat16_as_ushort(hb) << 16) | __bfloat16_as_ushort(ha);
    __nv_bfloat16 ga = __float2bfloat16(a - __bfloat162float(ha));
    __nv_bfloat16 gb = __float2bfloat16(b - __bfloat162float(hb));
    lo = ((uint32_t)__bfloat16_as_ushort(gb) << 16) | __bfloat16_as_ushort(ga);
}

// ---------------------------------------------------------------------------
// Flash attention with mma.sync bf16x3 (error-compensated)
// 8 warps; warp w owns q-rows [w*16, w*16+16)
// ---------------------------------------------------------------------------
__global__ void __launch_bounds__(256, 1) attn_kernel(const float* __restrict__ Kg,
                                                      const float* __restrict__ Qg,
                                                      const float* __restrict__ Vg) {
    extern __shared__ char sm[];
    const uint32_t smb = smem_u32(sm);
    const int tid = threadIdx.x;
    const int wid = tid >> 5;
    const int lane = tid & 31;
    const int l15 = lane & 15;

    const int qt = blockIdx.x;
    const int h = blockIdx.y;
    const int b = blockIdx.z;
    const int q0 = qt * BM;

    const float* Qbase = Qg + ((size_t)b * NN) * DD + h * HD;
    const float* Kbase = Kg + ((size_t)b * NN) * DD + h * HD;
    const float* Vbase = Vg + ((size_t)b * NN) * DD + h * HD;

    // ---- prologue: Q tile (scaled by 1/TEMP = exact 2^-3) -> QH/QL smem ----
    #pragma unroll
    for (int i = 0; i < 8; ++i) {
        int idx = tid + i * 256;
        int r = idx >> 4;
        int c4 = (idx & 15) << 2;
        float4 q = *(const float4*)(Qbase + (size_t)(q0 + r) * DD + c4);
        float v[4] = {q.x * 0.125f, q.y * 0.125f, q.z * 0.125f, q.w * 0.125f};
        uint2 hi, lo;
        split4(v, hi, lo);
        uint32_t off = (uint32_t)(r * STR + c4) * 2;
        *(uint2*)(sm + OF_QH + off) = hi;
        *(uint2*)(sm + OF_QL + off) = lo;
    }
    __syncthreads();

    // ---- hoist Q fragments (A of m16n8k16) into registers ----
    uint32_t qh[4][4], ql[4][4];
    {
        int lr = lane & 7, lm = lane >> 3;
        int qrow = wid * 16 + lr + (lm & 1) * 8;
        #pragma unroll
        for (int ks = 0; ks < 4; ++ks) {
            int col = ks * 16 + (lm >> 1) * 8;
            uint32_t off = (uint32_t)(qrow * STR + col) * 2;
            ldsm_x4(qh[ks], smb + OF_QH + off);
            ldsm_x4(ql[ks], smb + OF_QL + off);
        }
    }

    float oacc[8][4] = {};
    float rs0 = 0.f, rs1 = 0.f;

    for (int kt = 0; kt < NITER; ++kt) {
        __syncthreads();  // protect K/V smem from overwrite while prev iter in flight

        // ---- load K and V tiles, split hi/lo ----
        #pragma unroll
        for (int i = 0; i < 8; ++i) {
            int idx = tid + i * 256;
            int r = idx >> 4;
            int c4 = (idx & 15) << 2;
            uint32_t off = (uint32_t)(r * STR + c4) * 2;

            float4 k4 = *(const float4*)(Kbase + (size_t)(kt * BKV + r) * DD + c4);
            float kv[4] = {k4.x, k4.y, k4.z, k4.w};
            uint2 hi, lo;
            split4(kv, hi, lo);
            *(uint2*)(sm + OF_KH + off) = hi;
            *(uint2*)(sm + OF_KL + off) = lo;

            float4 v4 = *(const float4*)(Vbase + (size_t)(kt * BKV + r) * DD + c4);
            float vv[4] = {v4.x, v4.y, v4.z, v4.w};
            split4(vv, hi, lo);
            *(uint2*)(sm + OF_VH + off) = hi;
            *(uint2*)(sm + OF_VL + off) = lo;
        }
        __syncthreads();

        // ---- S = Q K^T (16 n-tiles x 4 k-steps x 3 combos) ----
        float sacc[16][4] = {};
        #pragma unroll
        for (int ks = 0; ks < 4; ++ks) {
            #pragma unroll
            for (int nt = 0; nt < 16; ++nt) {
                int krow = nt * 8 + (l15 & 7);
                int kcol = ks * 16 + (l15 >> 3) * 8;
                uint32_t off = (uint32_t)(krow * STR + kcol) * 2;
                uint32_t kh0, kh1, kl0, kl1;
                ldsm_x2(kh0, kh1, smb + OF_KH + off);
                ldsm_x2(kl0, kl1, smb + OF_KL + off);
                mma16816(sacc[nt], qh[ks], kh0, kh1);
                mma16816(sacc[nt], qh[ks], kl0, kl1);
                mma16816(sacc[nt], ql[ks], kh0, kh1);
            }
        }

        // ---- softmax (no max shift; |S|<~6) + build P fragments ----
        uint32_t pha[8][4], pla[8][4];
        #pragma unroll
        for (int c = 0; c < 8; ++c) {
            int t0 = 2 * c, t1 = 2 * c + 1;
            float e00 = __expf(sacc[t0][0]), e01 = __expf(sacc[t0][1]);
            float e02 = __expf(sacc[t0][2]), e03 = __expf(sacc[t0][3]);
            float e10 = __expf(sacc[t1][0]), e11 = __expf(sacc[t1][1]);
            float e12 = __expf(sacc[t1][2]), e13 = __expf(sacc[t1][3]);
            rs0 += (e00 + e01) + (e10 + e11);
            rs1 += (e02 + e03) + (e12 + e13);
            split2(e00, e01, pha[c][0], pla[c][0]);
            split2(e02, e03, pha[c][1], pla[c][1]);
            split2(e10, e11, pha[c][2], pla[c][2]);
            split2(e12, e13, pha[c][3], pla[c][3]);
        }

        // ---- O += P V (8 hd n-tiles x 8 k-chunks x 3 combos) ----
        #pragma unroll
        for (int c = 0; c < 8; ++c) {
            #pragma unroll
            for (int nt2 = 0; nt2 < 8; ++nt2) {
                int vrow = c * 16 + (l15 >> 3) * 8 + (l15 & 7);
                int vcol = nt2 * 8;
                uint32_t off = (uint32_t)(vrow * STR + vcol) * 2;
                uint32_t vh0, vh1, vl0, vl1;
                ldsm_x2t(vh0, vh1, smb + OF_VH + off);
                ldsm_x2t(vl0, vl1, smb + OF_VL + off);
                mma16816(oacc[nt2], pha[c], vh0, vh1);
                mma16816(oacc[nt2], pha[c], vl0, vl1);
                mma16816(oacc[nt2], pla[c], vh0, vh1);
            }
        }
    }

    // ---- rowsum reduce across quad (lanes sharing a row) ----
    rs0 += __shfl_xor_sync(0xffffffffu, rs0, 1);
    rs0 += __shfl_xor_sync(0xffffffffu, rs0, 2);
    rs1 += __shfl_xor_sync(0xffffffffu, rs1, 1);
    rs1 += __shfl_xor_sync(0xffffffffu, rs1, 2);
    float inv0 = 1.0f / rs0;
    float inv1 = 1.0f / rs1;

    // ---- epilogue: normalize + write to g_att ----
    int rowa = q0 + wid * 16 + (lane >> 2);
    float* Ob = g_att + ((size_t)(b * NN + rowa)) * DD + h * HD;
    #pragma unroll
    for (int nt2 = 0; nt2 < 8; ++nt2) {
        int col = nt2 * 8 + (lane & 3) * 2;
        float2 w0 = {oacc[nt2][0] * inv0, oacc[nt2][1] * inv0};
        *(float2*)(Ob + col) = w0;
        float2 w1 = {oacc[nt2][2] * inv1, oacc[nt2][3] * inv1};
        *(float2*)(Ob + (size_t)8 * DD + col) = w1;
    }
}

// ---------------------------------------------------------------------------
// Projection: out[m][n] = bias[n] + sum_k X[m][k] * W[n][k]  (fp32, from R1)
// ---------------------------------------------------------------------------
#define LDp 68
__global__ __launch_bounds__(256) void proj_kernel(const float* __restrict__ Wc,
                                                   const float* __restrict__ bias,
                                                   float* __restrict__ out) {
    __shared__ float Xt[64][LDp];
    __shared__ float Wt[64][LDp];

    const int n0 = blockIdx.x * 64;
    const int m0 = blockIdx.y * 64;
    const int t = threadIdx.x;
    const int tx = t & 15, ty = t >> 4;
    const int r0 = ty * 4, c0 = tx * 4;

    float acc[4][4] = {};

    for (int k0 = 0; k0 < DD; k0 += 64) {
        __syncthreads();
        for (int i = t; i < 64 * 16; i += 256) {
            int r = i >> 4;
            int k4 = (i & 15) << 2;
            float4 xv = *(const float4*)(g_att + (size_t)(m0 + r) * DD + k0 + k4);
            Xt[k4 + 0][r] = xv.x; Xt[k4 + 1][r] = xv.y;
            Xt[k4 + 2][r] = xv.z; Xt[k4 + 3][r] = xv.w;
            float4 wv = *(const float4*)(Wc + (size_t)(n0 + r) * DD + k0 + k4);
            Wt[k4 + 0][r] = wv.x; Wt[k4 + 1][r] = wv.y;
            Wt[k4 + 2][r] = wv.z; Wt[k4 + 3][r] = wv.w;
        }
        __syncthreads();

        #pragma unroll 8
        for (int k = 0; k < 64; ++k) {
            float4 xv = *(const float4*)&Xt[k][r0];
            float4 wv = *(const float4*)&Wt[k][c0];
            acc[0][0] += xv.x * wv.x; acc[0][1] += xv.x * wv.y; acc[0][2] += xv.x * wv.z; acc[0][3] += xv.x * wv.w;
            acc[1][0] += xv.y * wv.x; acc[1][1] += xv.y * wv.y; acc[1][2] += xv.y * wv.z; acc[1][3] += xv.y * wv.w;
            acc[2][0] += xv.z * wv.x; acc[2][1] += xv.z * wv.y; acc[2][2] += xv.z * wv.z; acc[2][3] += xv.z * wv.w;
            acc[3][0] += xv.w * wv.x; acc[3][1] += xv.w * wv.y; acc[3][2] += xv.w * wv.z; acc[3][3] += xv.w * wv.w;
        }
    }

    float4 bv = *(const float4*)(bias + n0 + c0);
    #pragma unroll
    for (int i = 0; i < 4; ++i) {
        float4 ov;
        ov.x = acc[i][0] + bv.x;
        ov.y = acc[i][1] + bv.y;
        ov.z = acc[i][2] + bv.z;
        ov.w = acc[i][3] + bv.w;
        *(float4*)(out + (size_t)(m0 + r0 + i) * DD + n0 + c0) = ov;
    }
}

extern "C" void kernel_launch(void* const* d_in, const int* in_sizes, int n_in,
                              void* d_out, int out_size) {
    const float* Kg = (const float*)d_in[0];
    const float* Qg = (const float*)d_in[1];
    const float* Vg = (const float*)d_in[2];
    const float* Wc = (const float*)d_in[3];
    const float* bias = (const float*)d_in[4];
    float* out = (float*)d_out;

    cudaFuncSetAttribute(attn_kernel, cudaFuncAttributeMaxDynamicSharedMemorySize, SMEM_SZ);

    dim3 agrid(NN / BM, HH, BB);
    attn_kernel<<<agrid, 256, SMEM_SZ>>>(Kg, Qg, Vg);

    dim3 pgrid(DD / 64, (BB * NN) / 64);
    proj_kernel<<<pgrid, 256>>>(Wc, bias, out);
}